// round 7
// baseline (speedup 1.0000x reference)
#include <cuda_runtime.h>
#include <cuda_bf16.h>
#include <math.h>
#include <stdint.h>

// Problem constants
#define Bsz 2
#define Hh  64
#define Ww  24
#define Cc  256
#define Pp  8
#define HP  8
#define NHh 8
#define DK  32
#define KV  4
#define NROW (Bsz*Hh*Ww)       // 3072
#define NELEM (NROW*Cc)        // 786432
#define LBLK (HP*Ww)           // 192
#define LKEY (KV*LBLK)         // 768
#define KTOT (25*Cc)           // 6400 conv K
#define NSPLIT 3
#define NCHUNK 200             // 6400 / 32
#define WSZ ((long)Cc*Cc)

#define QK_SCALE (0.17677669529663687f * 1.44269504088896340f)

// ---------------- device scratch ----------------
// fp32 slots: 0:qp 1:kp 2:vp 3:xres 4:q2 5:k2 6:v2 7:rout 8:dummy 9..11:conv partials
__device__ float g_buf[12u * NELEM];
__device__ float g_loc[2 * 16 * Cc];
__device__ float g_bsum[Cc];
__device__ int   g_R[Bsz * Pp * KV];
__device__ __nv_bfloat16 g_x_hi[NELEM],   g_x_lo[NELEM];
__device__ __nv_bfloat16 g_act_hi[3u*NELEM], g_act_lo[3u*NELEM];
__device__ __nv_bfloat16 g_ctx_hi[NELEM], g_ctx_lo[NELEM];
__device__ __nv_bfloat16 g_kvg_hi[NELEM], g_kvg_lo[NELEM];
__device__ __nv_bfloat16 g_wt_hi[Cc * KTOT], g_wt_lo[Cc * KTOT];
__device__ __nv_bfloat16 g_w8_hi[8u*Cc*Cc], g_w8_lo[8u*Cc*Cc];

// ---------------- packed f32x2 helpers ----------------
__device__ __forceinline__ unsigned long long pk2(float lo, float hi) {
    unsigned long long r;
    asm("mov.b64 %0, {%1, %2};" : "=l"(r)
        : "r"(__float_as_uint(lo)), "r"(__float_as_uint(hi)));
    return r;
}
__device__ __forceinline__ unsigned long long ffma2(unsigned long long a,
                                                    unsigned long long b,
                                                    unsigned long long c) {
    unsigned long long d;
    asm("fma.rn.f32x2 %0, %1, %2, %3;" : "=l"(d) : "l"(a), "l"(b), "l"(c));
    return d;
}
__device__ __forceinline__ unsigned long long fmul2(unsigned long long a,
                                                    unsigned long long b) {
    unsigned long long d;
    asm("mul.rn.f32x2 %0, %1, %2;" : "=l"(d) : "l"(a), "l"(b));
    return d;
}
__device__ __forceinline__ float2 upk2(unsigned long long v) {
    unsigned int lo, hi;
    asm("mov.b64 {%0, %1}, %2;" : "=r"(lo), "=r"(hi) : "l"(v));
    return make_float2(__uint_as_float(lo), __uint_as_float(hi));
}
__device__ __forceinline__ float ex2f(float x) {
    float r;
    asm("ex2.approx.ftz.f32 %0, %1;" : "=f"(r) : "f"(x));
    return r;
}

// ---------------- warp MMA helpers ----------------
__device__ __forceinline__ uint32_t smem_u32(const void* p) {
    uint32_t a;
    asm("{ .reg .u64 t; cvta.to.shared.u64 t, %1; cvt.u32.u64 %0, t; }"
        : "=r"(a) : "l"(p));
    return a;
}
#define SWZ64(o) ((o) ^ (((o) >> 3) & 0x30))

__device__ __forceinline__ void ldsm4(uint32_t* r, uint32_t addr) {
    asm volatile("ldmatrix.sync.aligned.m8n8.x4.shared.b16 {%0,%1,%2,%3}, [%4];"
                 : "=r"(r[0]), "=r"(r[1]), "=r"(r[2]), "=r"(r[3]) : "r"(addr));
}
__device__ __forceinline__ void mma_bf16(float* c, const uint32_t* a, const uint32_t* b) {
    asm volatile(
        "mma.sync.aligned.m16n8k16.row.col.f32.bf16.bf16.f32 "
        "{%0,%1,%2,%3}, {%4,%5,%6,%7}, {%8,%9}, {%0,%1,%2,%3};"
        : "+f"(c[0]), "+f"(c[1]), "+f"(c[2]), "+f"(c[3])
        : "r"(a[0]), "r"(a[1]), "r"(a[2]), "r"(a[3]), "r"(b[0]), "r"(b[1]));
}

// ================= tensor-core projection GEMM, 64x128 tile, 2 CTA/SM =================
struct GemmSetT {
    const __nv_bfloat16 *Ah[4], *Al[4], *Bh[4], *Bl[4];
    const float* bias[4];
    float* C[4];
    __nv_bfloat16 *Ch[4], *Cl[4];
};

__global__ __launch_bounds__(256, 2)
void gemm_mma_kernel(GemmSetT gs)
{
    __shared__ char smem[24576];
    const uint32_t sb = smem_u32(smem);
    const uint32_t A_HI = sb, A_LO = sb + 4096, B_HI = sb + 8192, B_LO = sb + 16384;

    const int z = blockIdx.z;
    const __nv_bfloat16* __restrict__ Ah = gs.Ah[z];
    const __nv_bfloat16* __restrict__ Al = gs.Al[z];
    const __nv_bfloat16* __restrict__ Bh = gs.Bh[z];
    const __nv_bfloat16* __restrict__ Bl = gs.Bl[z];
    const float* __restrict__ bias = gs.bias[z];
    float* __restrict__ C = gs.C[z];
    __nv_bfloat16* __restrict__ Ch = gs.Ch[z];
    __nv_bfloat16* __restrict__ Cl = gs.Cl[z];

    const int tid  = threadIdx.x;
    const int wid  = tid >> 5;
    const int lane = tid & 31;
    const int m0 = blockIdx.x * 64;
    const int n0 = blockIdx.y * 128;
    const int wm = wid & 1;
    const int wn = wid >> 1;

    const int a_row = tid >> 2;         // 0..63
    const int a_seg = tid & 3;
    int b_row[2];
    b_row[0] = tid >> 2;                // 0..63
    b_row[1] = (tid >> 2) + 64;         // 64..127
    const int b_seg = tid & 3;

    float acc[2][4][4];
#pragma unroll
    for (int i = 0; i < 2; i++)
#pragma unroll
        for (int j = 0; j < 4; j++)
#pragma unroll
            for (int q = 0; q < 4; q++) acc[i][j][q] = 0.f;

    uint4 rAh, rAl, rBh[2], rBl[2];
    {
        const long aoff = (long)(m0 + a_row) * Cc + a_seg * 8;
        rAh = *(const uint4*)(Ah + aoff);
        rAl = *(const uint4*)(Al + aoff);
#pragma unroll
        for (int i = 0; i < 2; i++) {
            const long boff = (long)(n0 + b_row[i]) * Cc + b_seg * 8;
            rBh[i] = *(const uint4*)(Bh + boff);
            rBl[i] = *(const uint4*)(Bl + boff);
        }
    }

    for (int c = 0; c < 8; c++) {
        __syncthreads();
        {
            const uint32_t soA = SWZ64((uint32_t)(a_row * 64 + a_seg * 16));
            *(uint4*)(smem + soA)        = rAh;
            *(uint4*)(smem + 4096 + soA) = rAl;
#pragma unroll
            for (int i = 0; i < 2; i++) {
                const uint32_t soB = SWZ64((uint32_t)(b_row[i] * 64 + b_seg * 16));
                *(uint4*)(smem + 8192 + soB)  = rBh[i];
                *(uint4*)(smem + 16384 + soB) = rBl[i];
            }
        }
        __syncthreads();

        if (c + 1 < 8) {
            const int kb = (c + 1) * 32;
            const long aoff = (long)(m0 + a_row) * Cc + kb + a_seg * 8;
            rAh = *(const uint4*)(Ah + aoff);
            rAl = *(const uint4*)(Al + aoff);
#pragma unroll
            for (int i = 0; i < 2; i++) {
                const long boff = (long)(n0 + b_row[i]) * Cc + kb + b_seg * 8;
                rBh[i] = *(const uint4*)(Bh + boff);
                rBl[i] = *(const uint4*)(Bl + boff);
            }
        }

#pragma unroll
        for (int kst = 0; kst < 2; kst++) {
            uint32_t ahi[2][4], alo[2][4];
#pragma unroll
            for (int mh = 0; mh < 2; mh++) {
                const int tile = lane >> 3;
                const int row = wm * 32 + mh * 16 + ((tile & 1) << 3) + (lane & 7);
                const int unit = kst * 2 + (tile >> 1);
                const uint32_t so = SWZ64((uint32_t)(row * 64 + unit * 16));
                ldsm4(ahi[mh], A_HI + so);
                ldsm4(alo[mh], A_LO + so);
            }
            uint32_t bhi[4][2], blo[4][2];
#pragma unroll
            for (int ng = 0; ng < 2; ng++) {
                const int tile = lane >> 3;
                const int row = wn * 32 + ng * 16 + ((tile >> 1) << 3) + (lane & 7);
                const int unit = kst * 2 + (tile & 1);
                const uint32_t so = SWZ64((uint32_t)(row * 64 + unit * 16));
                uint32_t th[4], tl[4];
                ldsm4(th, B_HI + so);
                ldsm4(tl, B_LO + so);
                bhi[ng * 2][0] = th[0]; bhi[ng * 2][1] = th[1];
                bhi[ng * 2 + 1][0] = th[2]; bhi[ng * 2 + 1][1] = th[3];
                blo[ng * 2][0] = tl[0]; blo[ng * 2][1] = tl[1];
                blo[ng * 2 + 1][0] = tl[2]; blo[ng * 2 + 1][1] = tl[3];
            }
#pragma unroll
            for (int mh = 0; mh < 2; mh++)
#pragma unroll
                for (int nt = 0; nt < 4; nt++) {
                    mma_bf16(acc[mh][nt], ahi[mh], bhi[nt]);
                    mma_bf16(acc[mh][nt], alo[mh], bhi[nt]);
                    mma_bf16(acc[mh][nt], ahi[mh], blo[nt]);
                }
        }
    }

#pragma unroll
    for (int mh = 0; mh < 2; mh++) {
        const int mrow = m0 + wm * 32 + mh * 16 + (lane >> 2);
#pragma unroll
        for (int nt = 0; nt < 4; nt++) {
            const int n = n0 + wn * 32 + nt * 8 + (lane & 3) * 2;
            const float2 bi = *(const float2*)&bias[n];
            const float v0 = acc[mh][nt][0] + bi.x;
            const float v1 = acc[mh][nt][1] + bi.y;
            const float v2 = acc[mh][nt][2] + bi.x;
            const float v3 = acc[mh][nt][3] + bi.y;
            const size_t o0 = (size_t)mrow * Cc + n;
            const size_t o1 = (size_t)(mrow + 8) * Cc + n;
            *(float2*)&C[o0] = make_float2(v0, v1);
            *(float2*)&C[o1] = make_float2(v2, v3);
            if (Ch) {
                const __nv_bfloat16 h0 = __float2bfloat16(v0);
                const __nv_bfloat16 h1 = __float2bfloat16(v1);
                const __nv_bfloat16 h2 = __float2bfloat16(v2);
                const __nv_bfloat16 h3 = __float2bfloat16(v3);
                *(__nv_bfloat162*)&Ch[o0] = __nv_bfloat162(h0, h1);
                *(__nv_bfloat162*)&Ch[o1] = __nv_bfloat162(h2, h3);
                *(__nv_bfloat162*)&Cl[o0] = __nv_bfloat162(
                    __float2bfloat16(v0 - __bfloat162float(h0)),
                    __float2bfloat16(v1 - __bfloat162float(h1)));
                *(__nv_bfloat162*)&Cl[o1] = __nv_bfloat162(
                    __float2bfloat16(v2 - __bfloat162float(h2)),
                    __float2bfloat16(v3 - __bfloat162float(h3)));
            }
        }
    }
}

// ---------------- conv implicit GEMM, 64x128 tile, 2 CTA/SM ----------------
__global__ __launch_bounds__(256, 2)
void conv_mma_kernel(const __nv_bfloat16* __restrict__ a_hi,
                     const __nv_bfloat16* __restrict__ a_lo,
                     const __nv_bfloat16* __restrict__ b_hi,
                     const __nv_bfloat16* __restrict__ b_lo,
                     float* __restrict__ part)
{
    __shared__ char smem[24576];
    const uint32_t sb = smem_u32(smem);
    const uint32_t A_HI = sb, A_LO = sb + 4096, B_HI = sb + 8192, B_LO = sb + 16384;

    const int tid  = threadIdx.x;
    const int wid  = tid >> 5;
    const int lane = tid & 31;
    const int m0 = blockIdx.x * 64;
    const int n0 = blockIdx.y * 128;
    const int z  = blockIdx.z;
    const int cbeg = (z * NCHUNK) / 3;
    const int cend = ((z + 1) * NCHUNK) / 3;

    const int wm = wid & 1;
    const int wn = wid >> 1;

    const int a_row = tid >> 2;
    const int a_seg = tid & 3;
    const int am = m0 + a_row;
    const int a_b = am / (Hh * Ww);
    const int a_h = (am / Ww) % Hh;
    const int a_w = am % Ww;
    const long a_base = (long)a_b * Hh * Ww * Cc;
    int b_row[2];
    b_row[0] = tid >> 2;
    b_row[1] = (tid >> 2) + 64;
    const int b_seg = tid & 3;

    float acc[2][4][4];
#pragma unroll
    for (int i = 0; i < 2; i++)
#pragma unroll
        for (int j = 0; j < 4; j++)
#pragma unroll
            for (int q = 0; q < 4; q++) acc[i][j][q] = 0.f;

    uint4 rAh, rAl, rBh[2], rBl[2];
    {
        const int kb = cbeg * 32;
        const int patch = kb >> 8;
        const int kh = patch / 5, kw = patch % 5;
        const int ci0 = kb & 255;
        const int hh = a_h + kh - 2;
        const int ww = a_w + kw - 2;
        if (hh >= 0 && hh < Hh && ww >= 0 && ww < Ww) {
            const long off = a_base + ((long)hh * Ww + ww) * Cc + ci0 + a_seg * 8;
            rAh = *(const uint4*)(a_hi + off);
            rAl = *(const uint4*)(a_lo + off);
        } else {
            rAh = make_uint4(0, 0, 0, 0);
            rAl = make_uint4(0, 0, 0, 0);
        }
#pragma unroll
        for (int i = 0; i < 2; i++) {
            const long boff = (long)(n0 + b_row[i]) * KTOT + kb + b_seg * 8;
            rBh[i] = *(const uint4*)(b_hi + boff);
            rBl[i] = *(const uint4*)(b_lo + boff);
        }
    }

    for (int c = cbeg; c < cend; c++) {
        __syncthreads();
        {
            const uint32_t soA = SWZ64((uint32_t)(a_row * 64 + a_seg * 16));
            *(uint4*)(smem + soA)        = rAh;
            *(uint4*)(smem + 4096 + soA) = rAl;
#pragma unroll
            for (int i = 0; i < 2; i++) {
                const uint32_t soB = SWZ64((uint32_t)(b_row[i] * 64 + b_seg * 16));
                *(uint4*)(smem + 8192 + soB)  = rBh[i];
                *(uint4*)(smem + 16384 + soB) = rBl[i];
            }
        }
        __syncthreads();

        if (c + 1 < cend) {
            const int kb = (c + 1) * 32;
            const int patch = kb >> 8;
            const int kh = patch / 5, kw = patch % 5;
            const int ci0 = kb & 255;
            const int hh = a_h + kh - 2;
            const int ww = a_w + kw - 2;
            if (hh >= 0 && hh < Hh && ww >= 0 && ww < Ww) {
                const long off = a_base + ((long)hh * Ww + ww) * Cc + ci0 + a_seg * 8;
                rAh = *(const uint4*)(a_hi + off);
                rAl = *(const uint4*)(a_lo + off);
            } else {
                rAh = make_uint4(0, 0, 0, 0);
                rAl = make_uint4(0, 0, 0, 0);
            }
#pragma unroll
            for (int i = 0; i < 2; i++) {
                const long boff = (long)(n0 + b_row[i]) * KTOT + kb + b_seg * 8;
                rBh[i] = *(const uint4*)(b_hi + boff);
                rBl[i] = *(const uint4*)(b_lo + boff);
            }
        }

#pragma unroll
        for (int kst = 0; kst < 2; kst++) {
            uint32_t ahi[2][4], alo[2][4];
#pragma unroll
            for (int mh = 0; mh < 2; mh++) {
                const int tile = lane >> 3;
                const int row = wm * 32 + mh * 16 + ((tile & 1) << 3) + (lane & 7);
                const int unit = kst * 2 + (tile >> 1);
                const uint32_t so = SWZ64((uint32_t)(row * 64 + unit * 16));
                ldsm4(ahi[mh], A_HI + so);
                ldsm4(alo[mh], A_LO + so);
            }
            uint32_t bhi[4][2], blo[4][2];
#pragma unroll
            for (int ng = 0; ng < 2; ng++) {
                const int tile = lane >> 3;
                const int row = wn * 32 + ng * 16 + ((tile >> 1) << 3) + (lane & 7);
                const int unit = kst * 2 + (tile & 1);
                const uint32_t so = SWZ64((uint32_t)(row * 64 + unit * 16));
                uint32_t th[4], tl[4];
                ldsm4(th, B_HI + so);
                ldsm4(tl, B_LO + so);
                bhi[ng * 2][0] = th[0]; bhi[ng * 2][1] = th[1];
                bhi[ng * 2 + 1][0] = th[2]; bhi[ng * 2 + 1][1] = th[3];
                blo[ng * 2][0] = tl[0]; blo[ng * 2][1] = tl[1];
                blo[ng * 2 + 1][0] = tl[2]; blo[ng * 2 + 1][1] = tl[3];
            }
#pragma unroll
            for (int mh = 0; mh < 2; mh++)
#pragma unroll
                for (int nt = 0; nt < 4; nt++) {
                    mma_bf16(acc[mh][nt], ahi[mh], bhi[nt]);
                    mma_bf16(acc[mh][nt], alo[mh], bhi[nt]);
                    mma_bf16(acc[mh][nt], ahi[mh], blo[nt]);
                }
        }
    }

    float* base = part + (size_t)z * NELEM;
#pragma unroll
    for (int mh = 0; mh < 2; mh++) {
        const int mrow = m0 + wm * 32 + mh * 16 + (lane >> 2);
#pragma unroll
        for (int nt = 0; nt < 4; nt++) {
            const int n = n0 + wn * 32 + nt * 8 + (lane & 3) * 2;
            *(float2*)&base[(size_t)mrow * Cc + n] =
                make_float2(acc[mh][nt][0], acc[mh][nt][1]);
            *(float2*)&base[(size_t)(mrow + 8) * Cc + n] =
                make_float2(acc[mh][nt][2], acc[mh][nt][3]);
        }
    }
}

// ---------------- fused decompose: 8 proj weights + conv weight + x ----------------
struct DecompAll {
    const float *w[7];
    const float *wk, *wv;     // for wsum slot 7
    const float *convw;
    const float *x;
    const float *bk, *bv;
};

__global__ void decomp_all_kernel(DecompAll da)
{
    const int z = blockIdx.z;
    const int bx = blockIdx.x, by = blockIdx.y;
    const int tid = threadIdx.x;
    const int tx = tid & 31, ty = tid >> 5;

    __nv_bfloat16 *w8h = g_w8_hi, *w8l = g_w8_lo;
    __nv_bfloat16 *wth = g_wt_hi, *wtl = g_wt_lo;

    if (z <= 7) {
        if (bx >= 8) return;
        if (z == 7 && bx == 0 && by == 0)
            g_bsum[tid] = da.bk[tid] + da.bv[tid];
        __shared__ float tile[32][33];
        const int k0 = bx * 32, n0 = by * 32;
#pragma unroll
        for (int i = 0; i < 4; i++) {
            const long off = (long)(k0 + ty + i * 8) * Cc + n0 + tx;
            tile[ty + i * 8][tx] = (z < 7) ? da.w[z][off] : (da.wk[off] + da.wv[off]);
        }
        __syncthreads();
#pragma unroll
        for (int i = 0; i < 4; i++) {
            const float v = tile[tx][ty + i * 8];
            const __nv_bfloat16 h = __float2bfloat16(v);
            const long o = (long)z * WSZ + (long)(n0 + ty + i * 8) * Cc + k0 + tx;
            w8h[o] = h;
            w8l[o] = __float2bfloat16(v - __bfloat162float(h));
        }
    } else if (z == 8) {
        __shared__ float tile[32][33];
        const int k0 = bx * 32, n0 = by * 32;
#pragma unroll
        for (int i = 0; i < 4; i++)
            tile[ty + i * 8][tx] = da.convw[(long)(k0 + ty + i * 8) * Cc + n0 + tx];
        __syncthreads();
#pragma unroll
        for (int i = 0; i < 4; i++) {
            const float v = tile[tx][ty + i * 8];
            const __nv_bfloat16 h = __float2bfloat16(v);
            const long o = (long)(n0 + ty + i * 8) * KTOT + k0 + tx;
            wth[o] = h;
            wtl[o] = __float2bfloat16(v - __bfloat162float(h));
        }
    } else {
        const int idx = (by * 200 + bx) * 256 + tid;
        if (idx < NELEM / 4) {
            const float4 v = ((const float4*)da.x)[idx];
            __nv_bfloat16 h0 = __float2bfloat16(v.x), h1 = __float2bfloat16(v.y);
            __nv_bfloat16 h2 = __float2bfloat16(v.z), h3 = __float2bfloat16(v.w);
            ((__nv_bfloat162*)g_x_hi)[idx * 2]     = __nv_bfloat162(h0, h1);
            ((__nv_bfloat162*)g_x_hi)[idx * 2 + 1] = __nv_bfloat162(h2, h3);
            ((__nv_bfloat162*)g_x_lo)[idx * 2]     = __nv_bfloat162(
                __float2bfloat16(v.x - __bfloat162float(h0)),
                __float2bfloat16(v.y - __bfloat162float(h1)));
            ((__nv_bfloat162*)g_x_lo)[idx * 2 + 1] = __nv_bfloat162(
                __float2bfloat16(v.z - __bfloat162float(h2)),
                __float2bfloat16(v.w - __bfloat162float(h3)));
        }
    }
}

// ---------------- block mean pooling ----------------
__global__ void pool_kernel(const float* __restrict__ qp, const float* __restrict__ kp,
                            float* __restrict__ qloc, float* __restrict__ kloc)
{
    const int bp = blockIdx.x;
    const int c  = threadIdx.x;
    const float* qb = qp + (long)bp * LBLK * Cc + c;
    const float* kb = kp + (long)bp * LBLK * Cc + c;
    float sq = 0.f, sk = 0.f;
    for (int i = 0; i < LBLK; i++) { sq += qb[i * Cc]; sk += kb[i * Cc]; }
    qloc[bp * Cc + c] = sq * (1.f / (float)LBLK);
    kloc[bp * Cc + c] = sk * (1.f / (float)LBLK);
}

// ---------------- routing ----------------
__global__ void route_kernel(const float* __restrict__ qloc, const float* __restrict__ kloc,
                             int* __restrict__ R)
{
    const int bp = blockIdx.x;
    const int b  = bp / Pp;
    const int warp = threadIdx.x >> 5;
    const int lane = threadIdx.x & 31;
    __shared__ float s[8];
    const float* q = qloc + bp * Cc;
    const float* k = kloc + (b * Pp + warp) * Cc;
    float partial = 0.f;
    for (int c = lane; c < Cc; c += 32) partial += q[c] * k[c];
#pragma unroll
    for (int o = 16; o; o >>= 1) partial += __shfl_xor_sync(0xffffffff, partial, o);
    if (lane == 0) s[warp] = partial;
    __syncthreads();
    if (threadIdx.x == 0) {
        bool used[8] = {};
        for (int t = 0; t < KV; t++) {
            int best = 0; float bv = -1e30f;
            for (int j = 0; j < Pp; j++)
                if (!used[j] && s[j] > bv) { bv = s[j]; best = j; }
            used[best] = true;
            R[bp * KV + t] = best;
        }
    }
}

// ---------------- attention (MUFU ex2, writes ctx hi/lo) ----------------
#define KCHUNK 128
__global__ void attention_kernel(const float* __restrict__ q2,
                                 const float* __restrict__ k2,
                                 const float* __restrict__ v2,
                                 const int* __restrict__ R,
                                 __nv_bfloat16* __restrict__ ctx_hi,
                                 __nv_bfloat16* __restrict__ ctx_lo)
{
    __shared__ float Ks[KCHUNK * DK];
    __shared__ float Vs[KCHUNK * DK];
    __shared__ int   Rs[KV];

    const int blk = blockIdx.x;
    const int h = blk % NHh;
    const int p = (blk / NHh) % Pp;
    const int b = blk / (NHh * Pp);
    const int tid = threadIdx.x;

    if (tid < KV) Rs[tid] = R[(b * Pp + p) * KV + tid];

    const bool active = (tid < LBLK);
    unsigned long long qv2[DK / 2], acc2[DK / 2];
    float m = -1e30f, l = 0.f;
    if (active) {
        const float* qrow = q2 + ((long)((b * Pp + p) * LBLK + tid)) * Cc + h * DK;
#pragma unroll
        for (int d2 = 0; d2 < DK / 2; d2++) {
            qv2[d2] = pk2(qrow[2 * d2] * QK_SCALE, qrow[2 * d2 + 1] * QK_SCALE);
            acc2[d2] = 0ull;
        }
    }

    for (int ch = 0; ch < LKEY / KCHUNK; ch++) {
        __syncthreads();
        const int kg0 = ch * KCHUNK;
        for (int i = tid; i < KCHUNK * (DK / 4); i += blockDim.x) {
            const int row = i >> 3;
            const int d4  = (i & 7) * 4;
            const int kg  = kg0 + row;
            const int ks  = kg / LBLK;
            const int rr  = kg - ks * LBLK;
            const int r   = Rs[ks];
            const long base = ((long)(b * Pp + r) * LBLK + rr) * Cc + h * DK + d4;
            *(float4*)&Ks[row * DK + d4] = *(const float4*)&k2[base];
            *(float4*)&Vs[row * DK + d4] = *(const float4*)&v2[base];
        }
        __syncthreads();
        if (active) {
            for (int k = 0; k < KCHUNK; k++) {
                const unsigned long long* kr = (const unsigned long long*)&Ks[k * DK];
                unsigned long long s0 = 0ull, s1 = 0ull, s2 = 0ull, s3 = 0ull;
#pragma unroll
                for (int d2 = 0; d2 < DK / 2; d2 += 4) {
                    s0 = ffma2(qv2[d2 + 0], kr[d2 + 0], s0);
                    s1 = ffma2(qv2[d2 + 1], kr[d2 + 1], s1);
                    s2 = ffma2(qv2[d2 + 2], kr[d2 + 2], s2);
                    s3 = ffma2(qv2[d2 + 3], kr[d2 + 3], s3);
                }
                const float2 f0 = upk2(s0), f1 = upk2(s1), f2 = upk2(s2), f3 = upk2(s3);
                const float s = ((f0.x + f0.y) + (f1.x + f1.y)) + ((f2.x + f2.y) + (f3.x + f3.y));
                const float mnew = fmaxf(m, s);
                const float corr = ex2f(m - mnew);
                const float pe   = ex2f(s - mnew);
                l = fmaf(l, corr, pe);
                const unsigned long long cc = pk2(corr, corr);
                const unsigned long long pp = pk2(pe, pe);
                const unsigned long long* vr = (const unsigned long long*)&Vs[k * DK];
#pragma unroll
                for (int d2 = 0; d2 < DK / 2; d2++)
                    acc2[d2] = ffma2(acc2[d2], cc, fmul2(pp, vr[d2]));
                m = mnew;
            }
        }
    }

    if (active) {
        const float inv = 1.0f / l;
        const long base = ((long)((b * Pp + p) * LBLK + tid)) * Cc + h * DK;
#pragma unroll
        for (int d2 = 0; d2 < DK / 2; d2++) {
            float2 f = upk2(acc2[d2]);
            const float v0 = f.x * inv, v1 = f.y * inv;
            const __nv_bfloat16 h0 = __float2bfloat16(v0);
            const __nv_bfloat16 h1 = __float2bfloat16(v1);
            *(__nv_bfloat162*)&ctx_hi[base + 2 * d2] = __nv_bfloat162(h0, h1);
            *(__nv_bfloat162*)&ctx_lo[base + 2 * d2] = __nv_bfloat162(
                __float2bfloat16(v0 - __bfloat162float(h0)),
                __float2bfloat16(v1 - __bfloat162float(h1)));
        }
    }
}

// ---------------- fused residual add + LayerNorm ----------------
__global__ void add_ln_kernel(const float* __restrict__ a, const float* __restrict__ bsrc,
                              const float* __restrict__ g, const float* __restrict__ beta,
                              float* __restrict__ out)
{
    const int mrow = blockIdx.x;
    const int c = threadIdx.x;
    __shared__ float red[Cc];
    const float v = a[(long)mrow * Cc + c] + bsrc[(long)mrow * Cc + c];
    red[c] = v;
    __syncthreads();
    for (int s = Cc / 2; s > 0; s >>= 1) {
        if (c < s) red[c] += red[c + s];
        __syncthreads();
    }
    const float mean = red[0] * (1.f / (float)Cc);
    __syncthreads();
    const float d = v - mean;
    red[c] = d * d;
    __syncthreads();
    for (int s = Cc / 2; s > 0; s >>= 1) {
        if (c < s) red[c] += red[c + s];
        __syncthreads();
    }
    const float var = red[0] * (1.f / (float)Cc);
    out[(long)mrow * Cc + c] = d * rsqrtf(var + 1e-5f) * g[c] + beta[c];
}

__global__ void add_lnK_kernel(const float* __restrict__ a, const float* __restrict__ pbase,
                               const float* __restrict__ cb,
                               const float* __restrict__ g, const float* __restrict__ beta,
                               float* __restrict__ out)
{
    const int mrow = blockIdx.x;
    const int c = threadIdx.x;
    __shared__ float red[Cc];
    const long off = (long)mrow * Cc + c;
    float v = a[off] + cb[c];
#pragma unroll
    for (int s = 0; s < NSPLIT; s++) v += pbase[off + (size_t)s * NELEM];
    red[c] = v;
    __syncthreads();
    for (int s = Cc / 2; s > 0; s >>= 1) {
        if (c < s) red[c] += red[c + s];
        __syncthreads();
    }
    const float mean = red[0] * (1.f / (float)Cc);
    __syncthreads();
    const float d = v - mean;
    red[c] = d * d;
    __syncthreads();
    for (int s = Cc / 2; s > 0; s >>= 1) {
        if (c < s) red[c] += red[c + s];
        __syncthreads();
    }
    const float var = red[0] * (1.f / (float)Cc);
    out[off] = d * rsqrtf(var + 1e-5f) * g[c] + beta[c];
}

// ---------------- launcher ----------------
extern "C" void kernel_launch(void* const* d_in, const int* in_sizes, int n_in,
                              void* d_out, int out_size)
{
    const float* x        = (const float*)d_in[0];
    const float* wq_proj  = (const float*)d_in[1];
    const float* bq_proj  = (const float*)d_in[2];
    const float* wk_proj  = (const float*)d_in[3];
    const float* bk_proj  = (const float*)d_in[4];
    const float* wv_proj  = (const float*)d_in[5];
    const float* bv_proj  = (const float*)d_in[6];
    const float* wq_a     = (const float*)d_in[7];
    const float* bq_a     = (const float*)d_in[8];
    const float* wk_a     = (const float*)d_in[9];
    const float* bk_a     = (const float*)d_in[10];
    const float* wv_a     = (const float*)d_in[11];
    const float* bv_a     = (const float*)d_in[12];
    const float* wo_a     = (const float*)d_in[13];
    const float* bo_a     = (const float*)d_in[14];
    const float* conv_w   = (const float*)d_in[15];
    const float* conv_b   = (const float*)d_in[16];
    const float* ln1_g    = (const float*)d_in[17];
    const float* ln1_b    = (const float*)d_in[18];
    const float* ln2_g    = (const float*)d_in[19];
    const float* ln2_b    = (const float*)d_in[20];
    float* out = (float*)d_out;

    float* buf = nullptr;   cudaGetSymbolAddress((void**)&buf, g_buf);
    float* loc = nullptr;   cudaGetSymbolAddress((void**)&loc, g_loc);
    float* bsum = nullptr;  cudaGetSymbolAddress((void**)&bsum, g_bsum);
    int*   Rp  = nullptr;   cudaGetSymbolAddress((void**)&Rp, g_R);
    __nv_bfloat16 *xh, *xl, *ah, *al, *cxh, *cxl, *kvh, *kvl, *wth, *wtl, *w8h, *w8l;
    cudaGetSymbolAddress((void**)&xh,  g_x_hi);
    cudaGetSymbolAddress((void**)&xl,  g_x_lo);
    cudaGetSymbolAddress((void**)&ah,  g_act_hi);
    cudaGetSymbolAddress((void**)&al,  g_act_lo);
    cudaGetSymbolAddress((void**)&cxh, g_ctx_hi);
    cudaGetSymbolAddress((void**)&cxl, g_ctx_lo);
    cudaGetSymbolAddress((void**)&kvh, g_kvg_hi);
    cudaGetSymbolAddress((void**)&kvl, g_kvg_lo);
    cudaGetSymbolAddress((void**)&wth, g_wt_hi);
    cudaGetSymbolAddress((void**)&wtl, g_wt_lo);
    cudaGetSymbolAddress((void**)&w8h, g_w8_hi);
    cudaGetSymbolAddress((void**)&w8l, g_w8_lo);

    float* qp    = buf + 0l * NELEM;
    float* kp    = buf + 1l * NELEM;
    float* vp    = buf + 2l * NELEM;
    float* xres  = buf + 3l * NELEM;
    float* q2    = buf + 4l * NELEM;
    float* k2    = buf + 5l * NELEM;
    float* v2    = buf + 6l * NELEM;
    float* rout  = buf + 7l * NELEM;
    float* dummy = buf + 8l * NELEM;
    float* cnvp  = buf + 9l * NELEM;
    float* qloc = loc;
    float* kloc = loc + 16 * Cc;

    // 1: all weight / input decomposition in one launch
    {
        DecompAll da;
        da.w[0] = wq_proj; da.w[1] = wk_proj; da.w[2] = wv_proj;
        da.w[3] = wq_a;    da.w[4] = wk_a;    da.w[5] = wv_a;    da.w[6] = wo_a;
        da.wk = wk_proj;   da.wv = wv_proj;
        da.convw = conv_w; da.x = x;
        da.bk = bk_proj;   da.bv = bv_proj;
        decomp_all_kernel<<<dim3(200, 8, 10), 256>>>(da);
    }

    // 2: q/k/v block projections + fused kvg = x@(wk+wv)+(bk+bv)
    {
        GemmSetT gs;
        for (int i = 0; i < 3; i++) {
            gs.Ah[i] = xh; gs.Al[i] = xl;
            gs.Bh[i] = w8h + i * WSZ; gs.Bl[i] = w8l + i * WSZ;
            gs.Ch[i] = ah + (long)i * NELEM; gs.Cl[i] = al + (long)i * NELEM;
        }
        gs.bias[0] = bq_proj; gs.bias[1] = bk_proj; gs.bias[2] = bv_proj;
        gs.C[0] = qp; gs.C[1] = kp; gs.C[2] = vp;
        gs.Ah[3] = xh; gs.Al[3] = xl;
        gs.Bh[3] = w8h + 7 * WSZ; gs.Bl[3] = w8l + 7 * WSZ;
        gs.bias[3] = bsum; gs.C[3] = dummy;
        gs.Ch[3] = kvh; gs.Cl[3] = kvl;
        gemm_mma_kernel<<<dim3(NROW / 64, Cc / 128, 4), 256>>>(gs);
    }

    // 3: attention head projections
    {
        GemmSetT gs;
        for (int i = 0; i < 3; i++) {
            gs.Ah[i] = ah + (long)i * NELEM; gs.Al[i] = al + (long)i * NELEM;
            gs.Bh[i] = w8h + (3 + i) * WSZ;  gs.Bl[i] = w8l + (3 + i) * WSZ;
            gs.Ch[i] = nullptr; gs.Cl[i] = nullptr;
        }
        gs.bias[0] = bq_a; gs.bias[1] = bk_a; gs.bias[2] = bv_a;
        gs.C[0] = q2; gs.C[1] = k2; gs.C[2] = v2;
        gs.Ah[3] = xh; gs.Al[3] = xl; gs.Bh[3] = w8h; gs.Bl[3] = w8l;
        gs.bias[3] = bq_a; gs.C[3] = dummy; gs.Ch[3] = nullptr; gs.Cl[3] = nullptr;
        gemm_mma_kernel<<<dim3(NROW / 64, Cc / 128, 3), 256>>>(gs);
    }

    // 4: conv via pipelined mma.sync (profiled slot)
    conv_mma_kernel<<<dim3(NROW / 64, Cc / 128, NSPLIT), 256>>>(kvh, kvl, wth, wtl, cnvp);

    // 5-6: routing
    pool_kernel<<<Bsz * Pp, Cc>>>(qp, kp, qloc, kloc);
    route_kernel<<<Bsz * Pp, 256>>>(qloc, kloc, Rp);

    // 7: routed attention (emits ctx hi/lo)
    attention_kernel<<<Bsz * Pp * NHh, 256>>>(q2, k2, v2, Rp, cxh, cxl);

    // 8: output projection
    {
        GemmSetT gs;
        gs.Ah[0] = cxh; gs.Al[0] = cxl;
        gs.Bh[0] = w8h + 6 * WSZ; gs.Bl[0] = w8l + 6 * WSZ;
        gs.bias[0] = bo_a; gs.C[0] = rout;
        gs.Ch[0] = nullptr; gs.Cl[0] = nullptr;
        for (int i = 1; i < 4; i++) {
            gs.Ah[i] = cxh; gs.Al[i] = cxl;
            gs.Bh[i] = w8h; gs.Bl[i] = w8l;
            gs.bias[i] = bo_a; gs.C[i] = rout;
            gs.Ch[i] = nullptr; gs.Cl[i] = nullptr;
        }
        gemm_mma_kernel<<<dim3(NROW / 64, Cc / 128, 1), 256>>>(gs);
    }

    // 9-10: LayerNorms
    add_ln_kernel<<<NROW, Cc>>>(x, rout, ln1_g, ln1_b, xres);
    add_lnK_kernel<<<NROW, Cc>>>(xres, cnvp, conv_b, ln2_g, ln2_b, out);
}